// round 9
// baseline (speedup 1.0000x reference)
#include <cuda_runtime.h>
#include <cuda_fp16.h>
#include <math.h>

// ---------------- scratch (no allocation allowed; __device__ globals) --------
#define MAX_N 100000
__device__ float  g_proj[MAX_N * 32];  // [n][0:16]=z@W1a, [n][16:32]=z@W1b+b1 (12.8 MB)
__device__ float4 g_Wfmt[32 * 32];     // [s][l] = {W1c[4s+j][l], j=0..3} (16 KB)
__device__ uint2  g_zh[MAX_N * 32];    // z in fp16, 256B per node row (25.6 MB)

// packed f32x2 ops (Blackwell — PTX-only, ptxas never auto-fuses)
#define FMA_F32X2(acc, a, b) \
    asm("fma.rn.f32x2 %0, %1, %2, %0;" : "+l"(acc) : "l"(a), "l"(b))
#define ADD_F32X2(out, a, b) \
    asm("add.rn.f32x2 %0, %1, %2;" : "=l"(out) : "l"(a), "l"(b))

__device__ __forceinline__ float2 cvt_h2(unsigned u) {
    __half2 h = *reinterpret_cast<__half2*>(&u);
    return __half22float2(h);
}

// ---------------- kernel 0: one-time W1 reformat into [s][l][4] --------------
__global__ void prep_W_kernel(const float* __restrict__ W1) {
    int idx = blockIdx.x * blockDim.x + threadIdx.x;   // flat float index 0..4095
    if (idx >= 32 * 128) return;
    int j = idx & 3;
    int l = (idx >> 2) & 31;
    int s = idx >> 7;
    int k = 4 * s + j;
    float v = (l < 16) ? W1[k * 16 + l] : W1[(128 + k) * 16 + (l - 16)];
    ((float*)g_Wfmt)[idx] = v;
}

// ---------------- kernel 1: per-node projection + fp16 z emission -----------
// 256 thr = 8 warps; warp computes 4 nodes x 32 cols (lane = col).
// 32 KB smem total (16 KB sZ tile + 16 KB sW) -> ~6 blocks/SM for real
// load/compute overlap across blocks. f32x2 packed FMA mainloop, b1 folded
// into cols 16..31, fp16 z copy emitted from sZ.
#define PROJ_BLOCK 256
#define NODES_PER_WARP 4
#define NODES_PER_BLOCK 32   // 8 warps * 4 nodes

__global__ __launch_bounds__(PROJ_BLOCK) void proj_kernel(
    const float* __restrict__ z, const float* __restrict__ b1, int N)
{
    __shared__ float4 sZ[NODES_PER_BLOCK * 32];   // 32 nodes x 128 f32 = 16 KB
    __shared__ float4 sW[32 * 32];                // 16 KB, [s*32 + lane] = k-quad
    const int tid = threadIdx.x;
    const int node0 = blockIdx.x * NODES_PER_BLOCK;

    #pragma unroll
    for (int i = 0; i < 1024 / PROJ_BLOCK; i++)   // coalesced 16KB weight copy
        sW[tid + i * PROJ_BLOCK] = g_Wfmt[tid + i * PROJ_BLOCK];

    const float4* z4 = (const float4*)z;
    #pragma unroll
    for (int i = 0; i < (NODES_PER_BLOCK * 32) / PROJ_BLOCK; i++) {
        int idx = tid + i * PROJ_BLOCK;
        int n = node0 + (idx >> 5);
        sZ[idx] = (n < N) ? z4[(size_t)n * 32 + (idx & 31)]
                          : make_float4(0.f, 0.f, 0.f, 0.f);
    }
    __syncthreads();

    const int warp = tid >> 5;
    const int lane = tid & 31;                       // = output column c
    const ulonglong2* zbase = (const ulonglong2*)(sZ + (warp * NODES_PER_WARP) * 32);
    const ulonglong2* sW2   = (const ulonglong2*)sW;

    unsigned long long acc[NODES_PER_WARP];          // packed {sum_even, sum_odd}
    #pragma unroll
    for (int n = 0; n < NODES_PER_WARP; n++) acc[n] = 0ull;

    #pragma unroll 8
    for (int s = 0; s < 32; s++) {
        ulonglong2 wv = sW2[s * 32 + lane];          // conflict-free LDS.128
        #pragma unroll
        for (int n = 0; n < NODES_PER_WARP; n++) {
            ulonglong2 zv = zbase[n * 32 + s];       // LDS.128 broadcast
            FMA_F32X2(acc[n], zv.x, wv.x);
            FMA_F32X2(acc[n], zv.y, wv.y);
        }
    }

    // fold b1 into the col-side (cols 16..31) so edge kernel skips it
    const float bias = (lane >= 16) ? __ldg(b1 + lane - 16) : 0.f;

    #pragma unroll
    for (int n = 0; n < NODES_PER_WARP; n++) {
        int node = node0 + warp * NODES_PER_WARP + n;
        if (node < N) {
            float2 p = *reinterpret_cast<float2*>(&acc[n]);
            g_proj[(size_t)node * 32 + lane] = p.x + p.y + bias;   // coalesced
        }
    }

    // fp16 emission from sZ (coalesced 8B stores)
    #pragma unroll
    for (int i = 0; i < (NODES_PER_BLOCK * 32) / PROJ_BLOCK; i++) {
        int idx = tid + i * PROJ_BLOCK;
        int node = node0 + (idx >> 5);
        if (node < N) {
            float4 v = sZ[idx];
            __half2 h0 = __floats2half2_rn(v.x, v.y);
            __half2 h1 = __floats2half2_rn(v.z, v.w);
            uint2 pk;
            pk.x = *reinterpret_cast<unsigned*>(&h0);
            pk.y = *reinterpret_cast<unsigned*>(&h1);
            g_zh[(size_t)node0 * 32 + idx] = pk;
        }
    }
}

// ---------------- kernel 2: per-edge dual head (fp16 dot, 4 edges/warp) ------
// 8 lanes per edge. Each lane loads 2x16B of z_row/z_col fp16 (256B per node
// row across the group), converts, accumulates with packed f32x2 FMA.
// Each lane owns 2 hidden units of the MLP head. (dot, t) reduced together
// as one packed f32x2 over 3 xor rounds.
__global__ __launch_bounds__(256) void edge_kernel(
    const int* __restrict__ ei,            // int32 (jax x64 disabled)
    const float* __restrict__ W2,
    const float* __restrict__ b2,
    float* __restrict__ out,
    int E)
{
    const int group = (int)((blockIdx.x * blockDim.x + threadIdx.x) >> 3);  // edge id
    const int l = threadIdx.x & 7;
    const bool valid = (group < E);
    const int e = valid ? group : (E - 1);        // clamp; keep warp converged

    const int row = __ldg(ei + e);
    const int col = __ldg(ei + (size_t)E + e);

    const uint4* zh = (const uint4*)g_zh;         // 16 x 16B per node row
    uint4 A0 = __ldg(zh + (size_t)row * 16 + l);
    uint4 A1 = __ldg(zh + (size_t)row * 16 + 8 + l);
    uint4 B0 = __ldg(zh + (size_t)col * 16 + l);
    uint4 B1 = __ldg(zh + (size_t)col * 16 + 8 + l);

    // packed f32x2 dot accumulation (8 FFMA2 instead of 16 FFMA)
    unsigned long long dacc = 0ull;
    {
        float2 a, b;
        unsigned long long pa_, pb_;
        #define DOT_STEP(au, bu) \
            a = cvt_h2(au); b = cvt_h2(bu); \
            pa_ = *reinterpret_cast<unsigned long long*>(&a); \
            pb_ = *reinterpret_cast<unsigned long long*>(&b); \
            FMA_F32X2(dacc, pa_, pb_)
        DOT_STEP(A0.x, B0.x); DOT_STEP(A0.y, B0.y);
        DOT_STEP(A0.z, B0.z); DOT_STEP(A0.w, B0.w);
        DOT_STEP(A1.x, B1.x); DOT_STEP(A1.y, B1.y);
        DOT_STEP(A1.z, B1.z); DOT_STEP(A1.w, B1.w);
        #undef DOT_STEP
    }
    float2 dp = *reinterpret_cast<float2*>(&dacc);
    float dot = dp.x + dp.y;

    // MLP head: lane owns hidden units 2l, 2l+1 (b1 pre-folded into proj col-side)
    float2 pa = *(const float2*)(g_proj + (size_t)row * 32 + 2 * l);
    float2 pb = *(const float2*)(g_proj + (size_t)col * 32 + 16 + 2 * l);
    float2 w2 = *(const float2*)(W2 + 2 * l);
    float h0 = fmaxf(pa.x + pb.x, 0.f);
    float h1 = fmaxf(pa.y + pb.y, 0.f);
    float t  = h0 * w2.x + h1 * w2.y;

    // reduce (dot, t) together as packed f32x2
    float2 pr = make_float2(dot, t);
    unsigned long long pk = *reinterpret_cast<unsigned long long*>(&pr);
    #pragma unroll
    for (int off = 4; off; off >>= 1) {
        unsigned long long other = __shfl_xor_sync(0xFFFFFFFFu, pk, off);
        ADD_F32X2(pk, pk, other);
    }

    if (l == 0 && valid) {
        float2 r = *reinterpret_cast<float2*>(&pk);
        out[e] = r.x;
        float x = r.y + __ldg(b2);
        // softplus = max(x,0) + log1p(exp(-|x|))
        out[(size_t)E + e] = fmaxf(x, 0.f) + log1pf(__expf(-fabsf(x)));
    }
}

// ---------------- launch ----------------------------------------------------
extern "C" void kernel_launch(void* const* d_in, const int* in_sizes, int n_in,
                              void* d_out, int out_size) {
    const float* z  = (const float*)d_in[0];      // [N,128] f32
    const int*   ei = (const int*)d_in[1];        // [2,E] int32
    const float* W1 = (const float*)d_in[2];      // [256,16]
    const float* b1 = (const float*)d_in[3];      // [16]
    const float* W2 = (const float*)d_in[4];      // [16,1]
    const float* b2 = (const float*)d_in[5];      // [1]
    float* out = (float*)d_out;                   // [2E]: adj_logits | weights

    const int N = in_sizes[0] / 128;
    const int E = in_sizes[1] / 2;

    prep_W_kernel<<<(32 * 128 + 255) / 256, 256>>>(W1);
    proj_kernel<<<(N + NODES_PER_BLOCK - 1) / NODES_PER_BLOCK, PROJ_BLOCK>>>(z, b1, N);
    edge_kernel<<<((size_t)E * 8 + 255) / 256, 256>>>(ei, W2, b2, out, E);
}

// round 10
// speedup vs baseline: 1.0891x; 1.0891x over previous
#include <cuda_runtime.h>
#include <cuda_fp16.h>
#include <math.h>

// ---------------- scratch (no allocation allowed; __device__ globals) --------
#define MAX_N 100000
__device__ float  g_proj[MAX_N * 32];  // [n][0:16]=z@W1a, [n][16:32]=z@W1b+b1 (12.8 MB)
__device__ float4 g_Wfmt[32 * 32];     // [s][l] = {W1c[4s+j][l], j=0..3} (16 KB)
__device__ uint2  g_zh[MAX_N * 32];    // z in fp16, 256B per node row (25.6 MB)

// packed f32x2 ops (Blackwell — PTX-only, ptxas never auto-fuses)
#define FMA_F32X2(acc, a, b) \
    asm("fma.rn.f32x2 %0, %1, %2, %0;" : "+l"(acc) : "l"(a), "l"(b))
#define ADD_F32X2(out, a, b) \
    asm("add.rn.f32x2 %0, %1, %2;" : "=l"(out) : "l"(a), "l"(b))

__device__ __forceinline__ float2 cvt_h2(unsigned u) {
    __half2 h = *reinterpret_cast<__half2*>(&u);
    return __half22float2(h);
}

// ---------------- kernel 0: one-time W1 reformat into [s][l][4] --------------
__global__ void prep_W_kernel(const float* __restrict__ W1) {
    int idx = blockIdx.x * blockDim.x + threadIdx.x;   // flat float index 0..4095
    if (idx >= 32 * 128) return;
    int j = idx & 3;
    int l = (idx >> 2) & 31;
    int s = idx >> 7;
    int k = 4 * s + j;
    float v = (l < 16) ? W1[k * 16 + l] : W1[(128 + k) * 16 + (l - 16)];
    ((float*)g_Wfmt)[idx] = v;
}

// ---------------- kernel 1: per-node projection + fp16 z emission -----------
// 128 thr = 4 warps; warp computes 16 nodes x 32 cols (lane = col).
// Crossbar cost/node/s-iter = (4 + npw)/npw = 1.25 cyc at npw=16 (wv LDS.128
// amortized over 16 nodes; zv 16B broadcasts are the fixed N*32 term).
// 48 KB smem -> 4 blocks/SM. f32x2 packed FMA mainloop, b1 folded into cols
// 16..31, fp16 z copy emitted from sZ.
#define PROJ_BLOCK 128
#define NODES_PER_WARP 16
#define NODES_PER_BLOCK 64   // 4 warps * 16 nodes

__global__ __launch_bounds__(PROJ_BLOCK) void proj_kernel(
    const float* __restrict__ z, const float* __restrict__ b1, int N)
{
    __shared__ float4 sZ[NODES_PER_BLOCK * 32];   // 64 nodes x 128 f32 = 32 KB
    __shared__ float4 sW[32 * 32];                // 16 KB, [s*32 + lane] = k-quad
    const int tid = threadIdx.x;
    const int node0 = blockIdx.x * NODES_PER_BLOCK;

    #pragma unroll
    for (int i = 0; i < 1024 / PROJ_BLOCK; i++)   // coalesced 16KB weight copy
        sW[tid + i * PROJ_BLOCK] = g_Wfmt[tid + i * PROJ_BLOCK];

    const float4* z4 = (const float4*)z;
    #pragma unroll
    for (int i = 0; i < (NODES_PER_BLOCK * 32) / PROJ_BLOCK; i++) {
        int idx = tid + i * PROJ_BLOCK;
        int n = node0 + (idx >> 5);
        sZ[idx] = (n < N) ? z4[(size_t)n * 32 + (idx & 31)]
                          : make_float4(0.f, 0.f, 0.f, 0.f);
    }
    __syncthreads();

    const int warp = tid >> 5;
    const int lane = tid & 31;                       // = output column c
    const ulonglong2* zbase = (const ulonglong2*)(sZ + (warp * NODES_PER_WARP) * 32);
    const ulonglong2* sW2   = (const ulonglong2*)sW;

    unsigned long long acc[NODES_PER_WARP];          // packed {sum_even, sum_odd}
    #pragma unroll
    for (int n = 0; n < NODES_PER_WARP; n++) acc[n] = 0ull;

    #pragma unroll 4
    for (int s = 0; s < 32; s++) {
        ulonglong2 wv = sW2[s * 32 + lane];          // conflict-free LDS.128
        #pragma unroll
        for (int n = 0; n < NODES_PER_WARP; n++) {
            ulonglong2 zv = zbase[n * 32 + s];       // LDS.128 broadcast
            FMA_F32X2(acc[n], zv.x, wv.x);
            FMA_F32X2(acc[n], zv.y, wv.y);
        }
    }

    // fold b1 into the col-side (cols 16..31) so edge kernel skips it
    const float bias = (lane >= 16) ? __ldg(b1 + lane - 16) : 0.f;

    #pragma unroll
    for (int n = 0; n < NODES_PER_WARP; n++) {
        int node = node0 + warp * NODES_PER_WARP + n;
        if (node < N) {
            float2 p = *reinterpret_cast<float2*>(&acc[n]);
            g_proj[(size_t)node * 32 + lane] = p.x + p.y + bias;   // coalesced
        }
    }

    // fp16 emission from sZ (coalesced 8B stores)
    #pragma unroll
    for (int i = 0; i < (NODES_PER_BLOCK * 32) / PROJ_BLOCK; i++) {
        int idx = tid + i * PROJ_BLOCK;
        int node = node0 + (idx >> 5);
        if (node < N) {
            float4 v = sZ[idx];
            __half2 h0 = __floats2half2_rn(v.x, v.y);
            __half2 h1 = __floats2half2_rn(v.z, v.w);
            uint2 pk;
            pk.x = *reinterpret_cast<unsigned*>(&h0);
            pk.y = *reinterpret_cast<unsigned*>(&h1);
            g_zh[(size_t)node0 * 32 + idx] = pk;
        }
    }
}

// ---------------- kernel 2: per-edge dual head (fp16 dot, 4 edges/warp) ------
// 8 lanes per edge. Each lane loads 2x16B of z_row/z_col fp16 (256B per node
// row across the group), converts, accumulates with packed f32x2 FMA.
// Each lane owns 2 hidden units of the MLP head. (dot, t) reduced together
// as one packed f32x2 over 3 xor rounds.
__global__ __launch_bounds__(256) void edge_kernel(
    const int* __restrict__ ei,            // int32 (jax x64 disabled)
    const float* __restrict__ W2,
    const float* __restrict__ b2,
    float* __restrict__ out,
    int E)
{
    const int group = (int)((blockIdx.x * blockDim.x + threadIdx.x) >> 3);  // edge id
    const int l = threadIdx.x & 7;
    const bool valid = (group < E);
    const int e = valid ? group : (E - 1);        // clamp; keep warp converged

    const int row = __ldg(ei + e);
    const int col = __ldg(ei + (size_t)E + e);

    const uint4* zh = (const uint4*)g_zh;         // 16 x 16B per node row
    uint4 A0 = __ldg(zh + (size_t)row * 16 + l);
    uint4 A1 = __ldg(zh + (size_t)row * 16 + 8 + l);
    uint4 B0 = __ldg(zh + (size_t)col * 16 + l);
    uint4 B1 = __ldg(zh + (size_t)col * 16 + 8 + l);

    // packed f32x2 dot accumulation (8 FFMA2 instead of 16 FFMA)
    unsigned long long dacc = 0ull;
    {
        float2 a, b;
        unsigned long long pa_, pb_;
        #define DOT_STEP(au, bu) \
            a = cvt_h2(au); b = cvt_h2(bu); \
            pa_ = *reinterpret_cast<unsigned long long*>(&a); \
            pb_ = *reinterpret_cast<unsigned long long*>(&b); \
            FMA_F32X2(dacc, pa_, pb_)
        DOT_STEP(A0.x, B0.x); DOT_STEP(A0.y, B0.y);
        DOT_STEP(A0.z, B0.z); DOT_STEP(A0.w, B0.w);
        DOT_STEP(A1.x, B1.x); DOT_STEP(A1.y, B1.y);
        DOT_STEP(A1.z, B1.z); DOT_STEP(A1.w, B1.w);
        #undef DOT_STEP
    }
    float2 dp = *reinterpret_cast<float2*>(&dacc);
    float dot = dp.x + dp.y;

    // MLP head: lane owns hidden units 2l, 2l+1 (b1 pre-folded into proj col-side)
    float2 pa = *(const float2*)(g_proj + (size_t)row * 32 + 2 * l);
    float2 pb = *(const float2*)(g_proj + (size_t)col * 32 + 16 + 2 * l);
    float2 w2 = *(const float2*)(W2 + 2 * l);
    float h0 = fmaxf(pa.x + pb.x, 0.f);
    float h1 = fmaxf(pa.y + pb.y, 0.f);
    float t  = h0 * w2.x + h1 * w2.y;

    // reduce (dot, t) together as packed f32x2
    float2 pr = make_float2(dot, t);
    unsigned long long pk = *reinterpret_cast<unsigned long long*>(&pr);
    #pragma unroll
    for (int off = 4; off; off >>= 1) {
        unsigned long long other = __shfl_xor_sync(0xFFFFFFFFu, pk, off);
        ADD_F32X2(pk, pk, other);
    }

    if (l == 0 && valid) {
        float2 r = *reinterpret_cast<float2*>(&pk);
        out[e] = r.x;
        float x = r.y + __ldg(b2);
        // softplus = max(x,0) + log1p(exp(-|x|))
        out[(size_t)E + e] = fmaxf(x, 0.f) + log1pf(__expf(-fabsf(x)));
    }
}

// ---------------- launch ----------------------------------------------------
extern "C" void kernel_launch(void* const* d_in, const int* in_sizes, int n_in,
                              void* d_out, int out_size) {
    const float* z  = (const float*)d_in[0];      // [N,128] f32
    const int*   ei = (const int*)d_in[1];        // [2,E] int32
    const float* W1 = (const float*)d_in[2];      // [256,16]
    const float* b1 = (const float*)d_in[3];      // [16]
    const float* W2 = (const float*)d_in[4];      // [16,1]
    const float* b2 = (const float*)d_in[5];      // [1]
    float* out = (float*)d_out;                   // [2E]: adj_logits | weights

    const int N = in_sizes[0] / 128;
    const int E = in_sizes[1] / 2;

    prep_W_kernel<<<(32 * 128 + 255) / 256, 256>>>(W1);
    proj_kernel<<<(N + NODES_PER_BLOCK - 1) / NODES_PER_BLOCK, PROJ_BLOCK>>>(z, b1, N);
    edge_kernel<<<((size_t)E * 8 + 255) / 256, 256>>>(ei, W2, b2, out, E);
}

// round 11
// speedup vs baseline: 1.1276x; 1.0354x over previous
#include <cuda_runtime.h>
#include <cuda_fp16.h>
#include <math.h>

// ---------------- scratch (no allocation allowed; __device__ globals) --------
#define MAX_N 100000
__device__ float g_proj[MAX_N * 32];   // [n][0:16]=z@W1a, [n][16:32]=z@W1b+b1 (12.8 MB)
__device__ uint2 g_zh[MAX_N * 32];     // z in fp16, 256B per node row (25.6 MB)

// packed f32x2 ops (Blackwell — PTX-only, ptxas never auto-fuses)
#define FMA_F32X2(acc, a, b) \
    asm("fma.rn.f32x2 %0, %1, %2, %0;" : "+l"(acc) : "l"(a), "l"(b))
#define ADD_F32X2(out, a, b) \
    asm("add.rn.f32x2 %0, %1, %2;" : "=l"(out) : "l"(a), "l"(b))

__device__ __forceinline__ float2 cvt_h2(unsigned u) {
    __half2 h = *reinterpret_cast<__half2*>(&u);
    return __half22float2(h);
}

// ---------------- kernel 1: persistent double-buffered projection -----------
// 592 blocks (4/SM) x 64 thr (2 warps), npw=16 (best-measured crossbar point).
// Each block: build sW once (16KB coalesced LDG + conflict-free scatter), then
// loop 32-node tiles with cp.async double buffering: prefetch tile t+stride
// while computing tile t. b1 folded into cols 16..31; fp16 z copy emitted.
#define PROJ_THREADS 64
#define PNPW 16
#define TILE_NODES 32          // 2 warps * 16 nodes
#define PROJ_GRID 592          // 4 * 148

__global__ __launch_bounds__(PROJ_THREADS) void proj_kernel(
    const float* __restrict__ z, const float* __restrict__ W1,
    const float* __restrict__ b1, int N, int T)
{
    __shared__ float4 sW[32 * 32];           // 16 KB, [s*32 + lane] = k-quad
    __shared__ float4 sZ[2][TILE_NODES * 32]; // 2 x 16 KB double buffer
    const int tid = threadIdx.x;

    // ---- build sW once per block: stage raw W1 in sZ[0], scatter to sW ----
    {
        float* sraw = (float*)sZ[0];
        const float4* W14 = (const float4*)W1;       // 4096 floats = 1024 quads
        #pragma unroll
        for (int i = 0; i < 1024 / PROJ_THREADS; i++)
            ((float4*)sraw)[tid + i * PROJ_THREADS] = W14[tid + i * PROJ_THREADS];
        __syncthreads();
        #pragma unroll
        for (int i = 0; i < 1024 / PROJ_THREADS; i++) {
            int q = tid + i * PROJ_THREADS;          // output quad 0..1023
            int s = q >> 5;                          // k-quad index
            int l = q & 31;                          // output column
            float4 w;
            if (l < 16) {
                w.x = sraw[(4 * s + 0) * 16 + l];
                w.y = sraw[(4 * s + 1) * 16 + l];
                w.z = sraw[(4 * s + 2) * 16 + l];
                w.w = sraw[(4 * s + 3) * 16 + l];
            } else {
                w.x = sraw[(128 + 4 * s + 0) * 16 + (l - 16)];
                w.y = sraw[(128 + 4 * s + 1) * 16 + (l - 16)];
                w.z = sraw[(128 + 4 * s + 2) * 16 + (l - 16)];
                w.w = sraw[(128 + 4 * s + 3) * 16 + (l - 16)];
            }
            sW[q] = w;
        }
        __syncthreads();                             // sraw dead; sZ[0] reusable
    }

    const float4* z4 = (const float4*)z;
    const int warp = tid >> 5;
    const int lane = tid & 31;                       // = output column c
    const float bias = (lane >= 16) ? __ldg(b1 + lane - 16) : 0.f;
    const int stride = gridDim.x;

    // async prefetch of one 16KB tile (32 nodes) into buffer b
    auto issue_tile = [&](int tile, int b) {
        int node0 = tile * TILE_NODES;
        unsigned sbase = (unsigned)__cvta_generic_to_shared(&sZ[b][0]);
        #pragma unroll
        for (int i = 0; i < (TILE_NODES * 32) / PROJ_THREADS; i++) {
            int idx = tid + i * PROJ_THREADS;
            int n = min(node0 + (idx >> 5), N - 1);
            const float4* src = z4 + (size_t)n * 32 + (idx & 31);
            asm volatile("cp.async.cg.shared.global [%0], [%1], 16;"
                         :: "r"(sbase + idx * 16), "l"(src));
        }
        asm volatile("cp.async.commit_group;");
    };

    int t = blockIdx.x;
    int buf = 0;
    if (t < T) issue_tile(t, 0);

    while (t < T) {
        int nt = t + stride;
        if (nt < T) {
            issue_tile(nt, buf ^ 1);
            asm volatile("cp.async.wait_group %0;" :: "n"(1));
        } else {
            asm volatile("cp.async.wait_group %0;" :: "n"(0));
        }
        __syncthreads();

        // ---- compute tile t from sZ[buf] ----
        const int node0 = t * TILE_NODES;
        const ulonglong2* zbase =
            (const ulonglong2*)(sZ[buf] + (warp * PNPW) * 32);
        const ulonglong2* sW2 = (const ulonglong2*)sW;

        unsigned long long acc[PNPW];                // packed {sum_even, sum_odd}
        #pragma unroll
        for (int n = 0; n < PNPW; n++) acc[n] = 0ull;

        #pragma unroll 4
        for (int s = 0; s < 32; s++) {
            ulonglong2 wv = sW2[s * 32 + lane];      // conflict-free LDS.128
            #pragma unroll
            for (int n = 0; n < PNPW; n++) {
                ulonglong2 zv = zbase[n * 32 + s];   // LDS.128 broadcast
                FMA_F32X2(acc[n], zv.x, wv.x);
                FMA_F32X2(acc[n], zv.y, wv.y);
            }
        }

        #pragma unroll
        for (int n = 0; n < PNPW; n++) {
            int node = node0 + warp * PNPW + n;
            if (node < N) {
                float2 p = *reinterpret_cast<float2*>(&acc[n]);
                g_proj[(size_t)node * 32 + lane] = p.x + p.y + bias;  // coalesced
            }
        }

        // fp16 emission from sZ[buf] (coalesced 8B stores)
        #pragma unroll
        for (int i = 0; i < (TILE_NODES * 32) / PROJ_THREADS; i++) {
            int idx = tid + i * PROJ_THREADS;
            int node = node0 + (idx >> 5);
            if (node < N) {
                float4 v = sZ[buf][idx];
                __half2 h0 = __floats2half2_rn(v.x, v.y);
                __half2 h1 = __floats2half2_rn(v.z, v.w);
                uint2 pk;
                pk.x = *reinterpret_cast<unsigned*>(&h0);
                pk.y = *reinterpret_cast<unsigned*>(&h1);
                g_zh[(size_t)node0 * 32 + idx] = pk;
            }
        }
        __syncthreads();                             // readers done before buf reuse
        t = nt;
        buf ^= 1;
    }
}

// ---------------- kernel 2: per-edge dual head (fp16 dot, 4 edges/warp) ------
// 8 lanes per edge. Each lane loads 2x16B of z_row/z_col fp16 (256B per node
// row across the group), converts, accumulates with packed f32x2 FMA.
// Each lane owns 2 hidden units of the MLP head. (dot, t) reduced together
// as one packed f32x2 over 3 xor rounds.
__global__ __launch_bounds__(256) void edge_kernel(
    const int* __restrict__ ei,            // int32 (jax x64 disabled)
    const float* __restrict__ W2,
    const float* __restrict__ b2,
    float* __restrict__ out,
    int E)
{
    const int group = (int)((blockIdx.x * blockDim.x + threadIdx.x) >> 3);  // edge id
    const int l = threadIdx.x & 7;
    const bool valid = (group < E);
    const int e = valid ? group : (E - 1);        // clamp; keep warp converged

    const int row = __ldg(ei + e);
    const int col = __ldg(ei + (size_t)E + e);

    const uint4* zh = (const uint4*)g_zh;         // 16 x 16B per node row
    uint4 A0 = __ldg(zh + (size_t)row * 16 + l);
    uint4 A1 = __ldg(zh + (size_t)row * 16 + 8 + l);
    uint4 B0 = __ldg(zh + (size_t)col * 16 + l);
    uint4 B1 = __ldg(zh + (size_t)col * 16 + 8 + l);

    // packed f32x2 dot accumulation
    unsigned long long dacc = 0ull;
    {
        float2 a, b;
        unsigned long long pa_, pb_;
        #define DOT_STEP(au, bu) \
            a = cvt_h2(au); b = cvt_h2(bu); \
            pa_ = *reinterpret_cast<unsigned long long*>(&a); \
            pb_ = *reinterpret_cast<unsigned long long*>(&b); \
            FMA_F32X2(dacc, pa_, pb_)
        DOT_STEP(A0.x, B0.x); DOT_STEP(A0.y, B0.y);
        DOT_STEP(A0.z, B0.z); DOT_STEP(A0.w, B0.w);
        DOT_STEP(A1.x, B1.x); DOT_STEP(A1.y, B1.y);
        DOT_STEP(A1.z, B1.z); DOT_STEP(A1.w, B1.w);
        #undef DOT_STEP
    }
    float2 dp = *reinterpret_cast<float2*>(&dacc);
    float dot = dp.x + dp.y;

    // MLP head: lane owns hidden units 2l, 2l+1 (b1 pre-folded into proj col-side)
    float2 pa = *(const float2*)(g_proj + (size_t)row * 32 + 2 * l);
    float2 pb = *(const float2*)(g_proj + (size_t)col * 32 + 16 + 2 * l);
    float2 w2 = *(const float2*)(W2 + 2 * l);
    float h0 = fmaxf(pa.x + pb.x, 0.f);
    float h1 = fmaxf(pa.y + pb.y, 0.f);
    float t  = h0 * w2.x + h1 * w2.y;

    // reduce (dot, t) together as packed f32x2
    float2 pr = make_float2(dot, t);
    unsigned long long pk = *reinterpret_cast<unsigned long long*>(&pr);
    #pragma unroll
    for (int off = 4; off; off >>= 1) {
        unsigned long long other = __shfl_xor_sync(0xFFFFFFFFu, pk, off);
        ADD_F32X2(pk, pk, other);
    }

    if (l == 0 && valid) {
        float2 r = *reinterpret_cast<float2*>(&pk);
        out[e] = r.x;
        float x = r.y + __ldg(b2);
        // softplus = max(x,0) + log1p(exp(-|x|))
        out[(size_t)E + e] = fmaxf(x, 0.f) + log1pf(__expf(-fabsf(x)));
    }
}

// ---------------- launch ----------------------------------------------------
extern "C" void kernel_launch(void* const* d_in, const int* in_sizes, int n_in,
                              void* d_out, int out_size) {
    const float* z  = (const float*)d_in[0];      // [N,128] f32
    const int*   ei = (const int*)d_in[1];        // [2,E] int32
    const float* W1 = (const float*)d_in[2];      // [256,16]
    const float* b1 = (const float*)d_in[3];      // [16]
    const float* W2 = (const float*)d_in[4];      // [16,1]
    const float* b2 = (const float*)d_in[5];      // [1]
    float* out = (float*)d_out;                   // [2E]: adj_logits | weights

    const int N = in_sizes[0] / 128;
    const int E = in_sizes[1] / 2;

    const int T = (N + TILE_NODES - 1) / TILE_NODES;
    const int grid = (T < PROJ_GRID) ? T : PROJ_GRID;

    proj_kernel<<<grid, PROJ_THREADS>>>(z, W1, b1, N, T);
    edge_kernel<<<((size_t)E * 8 + 255) / 256, 256>>>(ei, W2, b2, out, E);
}

// round 12
// speedup vs baseline: 1.5331x; 1.3596x over previous
#include <cuda_runtime.h>
#include <cuda_fp16.h>
#include <math.h>

// ---------------- scratch (no allocation allowed; __device__ globals) --------
#define MAX_N 100000
__device__ float g_proj[MAX_N * 32];   // [n][0:16]=z@W1a, [n][16:32]=z@W1b+b1 (12.8 MB)
__device__ uint4 g_zh[MAX_N * 16];     // z in fp16, 256B per node row (25.6 MB)
__device__ uint2 g_Bfrag[1024];        // W1 as mma B-fragments [ks][ns][lane] (8 KB)

// packed f32x2 ops (Blackwell — PTX-only)
#define FMA_F32X2(acc, a, b) \
    asm("fma.rn.f32x2 %0, %1, %2, %0;" : "+l"(acc) : "l"(a), "l"(b))
#define ADD_F32X2(out, a, b) \
    asm("add.rn.f32x2 %0, %1, %2;" : "=l"(out) : "l"(a), "l"(b))

__device__ __forceinline__ float2 cvt_h2(unsigned u) {
    __half2 h = *reinterpret_cast<__half2*>(&u);
    return __half22float2(h);
}
__device__ __forceinline__ unsigned pack_h2(float a, float b) {
    __half2 h = __floats2half2_rn(a, b);
    return *reinterpret_cast<unsigned*>(&h);
}

// ---------------- kernel 1: z -> fp16 copy + B-fragment table ----------------
// One uint4 (8 halves) per thread from two float4 reads. Block 0 also builds
// the m16n8k16 B fragments of Wc (Wc[k][c] = c<16 ? W1[k][c] : W1[128+k][c-16]).
__global__ __launch_bounds__(256) void convert_kernel(
    const float* __restrict__ z, const float* __restrict__ W1, int N)
{
    int e = blockIdx.x * blockDim.x + threadIdx.x;
    if (e < N * 16) {
        const float4* z4 = (const float4*)z;
        float4 v0 = __ldg(z4 + 2 * (size_t)e);
        float4 v1 = __ldg(z4 + 2 * (size_t)e + 1);
        uint4 pk;
        pk.x = pack_h2(v0.x, v0.y);
        pk.y = pack_h2(v0.z, v0.w);
        pk.z = pack_h2(v1.x, v1.y);
        pk.w = pack_h2(v1.z, v1.w);
        g_zh[e] = pk;
    }
    if (blockIdx.x == 0) {
        for (int i = threadIdx.x; i < 1024; i += blockDim.x) {
            int l  = i & 31;
            int ns = (i >> 5) & 3;
            int ks = i >> 7;
            int tg = l & 3, g = l >> 2;
            int n  = ns * 8 + g;
            int k0 = ks * 16 + tg * 2;
            auto wc = [&](int k) {
                return (n < 16) ? __ldg(W1 + k * 16 + n)
                                : __ldg(W1 + (128 + k) * 16 + (n - 16));
            };
            uint2 frag;
            frag.x = pack_h2(wc(k0),     wc(k0 + 1));   // k0, k0+1
            frag.y = pack_h2(wc(k0 + 8), wc(k0 + 9));   // k0+8, k0+9
            g_Bfrag[i] = frag;
        }
    }
}

// ---------------- kernel 2: proj via mma.sync m16n8k16 (HMMA) ----------------
// Block = 128 thr (4 warps), tile = 64 nodes. cp.async zh tile into smem with
// 272B pitch (word = 68*row + k -> 32 distinct banks across the A-fragment
// lanes). Warp w computes nodes [w*16, w*16+16) x 32 cols: 8 k-steps x 4
// n-steps of mma. b1 folded into cols 16..31 at store.
#define PITCH 272
__global__ __launch_bounds__(128) void proj_mma_kernel(
    const float* __restrict__ b1, int N)
{
    __shared__ __align__(16) char sA[64 * PITCH];    // 17408 B
    const int tid = threadIdx.x;
    const int node0 = blockIdx.x * 64;

    // load 64 x 256B rows (1024 x 16B chunks), 8 per thread, coalesced
    {
        unsigned sbase = (unsigned)__cvta_generic_to_shared(sA);
        const char* src0 = (const char*)g_zh;
        #pragma unroll
        for (int i = 0; i < 8; i++) {
            int c = tid + i * 128;
            int row = c >> 4, cc = c & 15;
            int node = min(node0 + row, N - 1);
            asm volatile("cp.async.cg.shared.global [%0], [%1], 16;"
                :: "r"(sbase + row * PITCH + cc * 16),
                   "l"(src0 + (size_t)node * 256 + cc * 16));
        }
        asm volatile("cp.async.commit_group;");
        asm volatile("cp.async.wait_group 0;");
    }
    __syncthreads();

    const int w = tid >> 5, l = tid & 31;
    const int g = l >> 2, tg = l & 3;

    float c0[4], c1[4], c2[4], c3[4];
    #pragma unroll
    for (int ns = 0; ns < 4; ns++) { c0[ns] = c1[ns] = c2[ns] = c3[ns] = 0.f; }

    // A fragment addresses: rows (w*16+g) and (+8), halves k0=ks*16+tg*2 (+8)
    const char* aR0 = sA + (w * 16 + g) * PITCH + tg * 4;
    const char* aR1 = aR0 + 8 * PITCH;

    #pragma unroll
    for (int ks = 0; ks < 8; ks++) {
        unsigned a0 = *(const unsigned*)(aR0 + ks * 32);
        unsigned a1 = *(const unsigned*)(aR1 + ks * 32);
        unsigned a2 = *(const unsigned*)(aR0 + ks * 32 + 16);
        unsigned a3 = *(const unsigned*)(aR1 + ks * 32 + 16);
        #pragma unroll
        for (int ns = 0; ns < 4; ns++) {
            uint2 b = g_Bfrag[(ks * 4 + ns) * 32 + l];
            asm volatile(
                "mma.sync.aligned.m16n8k16.row.col.f32.f16.f16.f32 "
                "{%0,%1,%2,%3}, {%4,%5,%6,%7}, {%8,%9}, {%0,%1,%2,%3};"
                : "+f"(c0[ns]), "+f"(c1[ns]), "+f"(c2[ns]), "+f"(c3[ns])
                : "r"(a0), "r"(a1), "r"(a2), "r"(a3), "r"(b.x), "r"(b.y));
        }
    }

    // bias only applies to cols >= 16 (ns = 2, 3)
    float2 bias2 = *(const float2*)(b1 + tg * 2);
    float2 bias3 = *(const float2*)(b1 + 8 + tg * 2);

    const int n0 = node0 + w * 16 + g;
    const int n1 = n0 + 8;
    #pragma unroll
    for (int ns = 0; ns < 4; ns++) {
        float bx = (ns == 2) ? bias2.x : (ns == 3) ? bias3.x : 0.f;
        float by = (ns == 2) ? bias2.y : (ns == 3) ? bias3.y : 0.f;
        int coff = ns * 8 + tg * 2;
        if (n0 < N)
            *(float2*)(g_proj + (size_t)n0 * 32 + coff) =
                make_float2(c0[ns] + bx, c1[ns] + by);
        if (n1 < N)
            *(float2*)(g_proj + (size_t)n1 * 32 + coff) =
                make_float2(c2[ns] + bx, c3[ns] + by);
    }
}

// ---------------- kernel 3: per-edge dual head (fp16 dot, 4 edges/warp) ------
// unchanged from R10/R11 (measured 35.3 us)
__global__ __launch_bounds__(256) void edge_kernel(
    const int* __restrict__ ei,            // int32 (jax x64 disabled)
    const float* __restrict__ W2,
    const float* __restrict__ b2,
    float* __restrict__ out,
    int E)
{
    const int group = (int)((blockIdx.x * blockDim.x + threadIdx.x) >> 3);  // edge id
    const int l = threadIdx.x & 7;
    const bool valid = (group < E);
    const int e = valid ? group : (E - 1);        // clamp; keep warp converged

    const int row = __ldg(ei + e);
    const int col = __ldg(ei + (size_t)E + e);

    uint4 A0 = __ldg(g_zh + (size_t)row * 16 + l);
    uint4 A1 = __ldg(g_zh + (size_t)row * 16 + 8 + l);
    uint4 B0 = __ldg(g_zh + (size_t)col * 16 + l);
    uint4 B1 = __ldg(g_zh + (size_t)col * 16 + 8 + l);

    unsigned long long dacc = 0ull;
    {
        float2 a, b;
        unsigned long long pa_, pb_;
        #define DOT_STEP(au, bu) \
            a = cvt_h2(au); b = cvt_h2(bu); \
            pa_ = *reinterpret_cast<unsigned long long*>(&a); \
            pb_ = *reinterpret_cast<unsigned long long*>(&b); \
            FMA_F32X2(dacc, pa_, pb_)
        DOT_STEP(A0.x, B0.x); DOT_STEP(A0.y, B0.y);
        DOT_STEP(A0.z, B0.z); DOT_STEP(A0.w, B0.w);
        DOT_STEP(A1.x, B1.x); DOT_STEP(A1.y, B1.y);
        DOT_STEP(A1.z, B1.z); DOT_STEP(A1.w, B1.w);
        #undef DOT_STEP
    }
    float2 dp = *reinterpret_cast<float2*>(&dacc);
    float dot = dp.x + dp.y;

    // MLP head: lane owns hidden units 2l, 2l+1 (b1 pre-folded into proj col-side)
    float2 pa = *(const float2*)(g_proj + (size_t)row * 32 + 2 * l);
    float2 pb = *(const float2*)(g_proj + (size_t)col * 32 + 16 + 2 * l);
    float2 w2 = *(const float2*)(W2 + 2 * l);
    float h0 = fmaxf(pa.x + pb.x, 0.f);
    float h1 = fmaxf(pa.y + pb.y, 0.f);
    float t  = h0 * w2.x + h1 * w2.y;

    float2 pr = make_float2(dot, t);
    unsigned long long pk = *reinterpret_cast<unsigned long long*>(&pr);
    #pragma unroll
    for (int off = 4; off; off >>= 1) {
        unsigned long long other = __shfl_xor_sync(0xFFFFFFFFu, pk, off);
        ADD_F32X2(pk, pk, other);
    }

    if (l == 0 && valid) {
        float2 r = *reinterpret_cast<float2*>(&pk);
        out[e] = r.x;
        float x = r.y + __ldg(b2);
        out[(size_t)E + e] = fmaxf(x, 0.f) + log1pf(__expf(-fabsf(x)));
    }
}

// ---------------- launch ----------------------------------------------------
extern "C" void kernel_launch(void* const* d_in, const int* in_sizes, int n_in,
                              void* d_out, int out_size) {
    const float* z  = (const float*)d_in[0];      // [N,128] f32
    const int*   ei = (const int*)d_in[1];        // [2,E] int32
    const float* W1 = (const float*)d_in[2];      // [256,16]
    const float* b1 = (const float*)d_in[3];      // [16]
    const float* W2 = (const float*)d_in[4];      // [16,1]
    const float* b2 = (const float*)d_in[5];      // [1]
    float* out = (float*)d_out;                   // [2E]: adj_logits | weights

    const int N = in_sizes[0] / 128;
    const int E = in_sizes[1] / 2;

    convert_kernel<<<(N * 16 + 255) / 256, 256>>>(z, W1, N);
    proj_mma_kernel<<<(N + 63) / 64, 128>>>(b1, N);
    edge_kernel<<<((size_t)E * 8 + 255) / 256, 256>>>(ei, W2, b2, out, E);
}